// round 1
// baseline (speedup 1.0000x reference)
#include <cuda_runtime.h>
#include <math.h>

// Problem constants
#define Bb  4
#define Nn  2048
#define Dd  512
#define Hh  8
#define DHd 64

// Scratch (allocation-free rule: __device__ globals)
__device__ float g_Qh[(size_t)Bb * Hh * Nn * DHd];   // (B,H,N,DH)
__device__ float g_Kh[(size_t)Bb * Hh * Nn * DHd];
__device__ float g_Vh[(size_t)Bb * Hh * Nn * DHd];
__device__ float g_ctx[(size_t)Bb * Nn * Dd];        // (B,N,D) pre-Wo

// ---------------------------------------------------------------------------
// Kernel 1: QKV projection GEMM (out = x @ W^T + b), head-split into
// (B,H,N,DH), fused per-head LayerNorm for Q and K.
// Tile: BM=64, BN=64 (== one head), BK=16. 256 threads, 4x4 microtile.
// ---------------------------------------------------------------------------
__global__ __launch_bounds__(256) void qkv_kernel(
    const float* __restrict__ x,
    const float* __restrict__ Wq, const float* __restrict__ bq,
    const float* __restrict__ Wk, const float* __restrict__ bk,
    const float* __restrict__ Wv, const float* __restrict__ bv,
    const float* __restrict__ qg, const float* __restrict__ qb,
    const float* __restrict__ kg, const float* __restrict__ kb)
{
    const int t  = threadIdx.x;
    const int tx = t & 15;       // output-column group
    const int ty = t >> 4;       // output-row group
    const int bx = blockIdx.x;   // head (column tile), 0..7
    const int by = blockIdx.y;   // row tile, 0..127
    const int z  = blockIdx.z;   // 0=Q 1=K 2=V

    const float* W; const float* bvec; float* out;
    const float* gamma = nullptr; const float* beta = nullptr;
    if (z == 0)      { W = Wq; bvec = bq; out = g_Qh; gamma = qg; beta = qb; }
    else if (z == 1) { W = Wk; bvec = bk; out = g_Kh; gamma = kg; beta = kb; }
    else             { W = Wv; bvec = bv; out = g_Vh; }

    __shared__ float Xs[64][17];
    __shared__ float Ws[64][17];

    const int m0 = by * 64;
    const int n0 = bx * 64;

    float acc[4][4] = {};

    const int lr = t >> 2;        // 0..63
    const int lk = (t & 3) * 4;   // 0,4,8,12

    for (int k0 = 0; k0 < Dd; k0 += 16) {
        float4 xa = *(const float4*)(x + (size_t)(m0 + lr) * Dd + k0 + lk);
        float4 wa = *(const float4*)(W + (size_t)(n0 + lr) * Dd + k0 + lk);
        Xs[lr][lk + 0] = xa.x; Xs[lr][lk + 1] = xa.y;
        Xs[lr][lk + 2] = xa.z; Xs[lr][lk + 3] = xa.w;
        Ws[lr][lk + 0] = wa.x; Ws[lr][lk + 1] = wa.y;
        Ws[lr][lk + 2] = wa.z; Ws[lr][lk + 3] = wa.w;
        __syncthreads();
        #pragma unroll
        for (int kk = 0; kk < 16; kk++) {
            float rx[4], rw[4];
            #pragma unroll
            for (int i = 0; i < 4; i++) rx[i] = Xs[ty * 4 + i][kk];
            #pragma unroll
            for (int j = 0; j < 4; j++) rw[j] = Ws[tx * 4 + j][kk];
            #pragma unroll
            for (int i = 0; i < 4; i++)
                #pragma unroll
                for (int j = 0; j < 4; j++)
                    acc[i][j] += rx[i] * rw[j];
        }
        __syncthreads();
    }

    // bias add
    #pragma unroll
    for (int j = 0; j < 4; j++) {
        float bvv = bvec[n0 + tx * 4 + j];
        #pragma unroll
        for (int i = 0; i < 4; i++) acc[i][j] += bvv;
    }

    if (z < 2) {
        // per-head LayerNorm over the 64 tile columns (== one head).
        // Row r is held by the 16 lanes sharing ty -> width-16 xor shuffles.
        #pragma unroll
        for (int i = 0; i < 4; i++) {
            float s1 = acc[i][0] + acc[i][1] + acc[i][2] + acc[i][3];
            float s2 = acc[i][0] * acc[i][0] + acc[i][1] * acc[i][1]
                     + acc[i][2] * acc[i][2] + acc[i][3] * acc[i][3];
            #pragma unroll
            for (int off = 8; off; off >>= 1) {
                s1 += __shfl_xor_sync(0xffffffffu, s1, off, 16);
                s2 += __shfl_xor_sync(0xffffffffu, s2, off, 16);
            }
            float mean = s1 * (1.0f / 64.0f);
            float var  = s2 * (1.0f / 64.0f) - mean * mean;
            float rstd = rsqrtf(var + 1e-6f);
            #pragma unroll
            for (int j = 0; j < 4; j++) {
                int dh = tx * 4 + j;
                acc[i][j] = (acc[i][j] - mean) * rstd * gamma[dh] + beta[dh];
            }
        }
    }

    // write (B,H,N,DH): h = bx, dh = tx*4+j
    #pragma unroll
    for (int i = 0; i < 4; i++) {
        int m = m0 + ty * 4 + i;
        int b = m >> 11;          // m / 2048
        int n = m & (Nn - 1);
        float4 v4 = make_float4(acc[i][0], acc[i][1], acc[i][2], acc[i][3]);
        *(float4*)(out + (((size_t)b * Hh + bx) * Nn + n) * DHd + tx * 4) = v4;
    }
}

// ---------------------------------------------------------------------------
// Kernel 2: flash-style attention, fp32.
// grid = (N/64 q-tiles, B*H). 256 threads, 4x4 microtiles.
// smem tiles stride 65 for conflict-free access patterns.
// ---------------------------------------------------------------------------
#define LDPAD 65
#define SMEM_ATTN ((4 * 64 * LDPAD + 3 * 64 + 4 * 64) * (int)sizeof(float))

__global__ __launch_bounds__(256) void attn_kernel(const float* __restrict__ bias)
{
    extern __shared__ float sm[];
    float* Qs   = sm;                     // [64][65]
    float* Ks   = Qs + 64 * LDPAD;        // [64][65]
    float* Vs   = Ks + 64 * LDPAD;        // [64][65]  natural [c][d]
    float* Ss   = Vs + 64 * LDPAD;        // [64][65]  natural [r][c]
    float* mrow = Ss + 64 * LDPAD;        // 64
    float* lrow = mrow + 64;              // 64
    float* scl  = lrow + 64;              // 64
    float* red  = scl  + 64;              // 4*64

    const int t  = threadIdx.x;
    const int tx = t & 15;
    const int ty = t >> 4;
    const int qt = blockIdx.x;            // 0..31
    const int bh = blockIdx.y;            // 0..31
    const int b  = bh >> 3;
    const int h  = bh & 7;
    const int q0 = qt * 64;

    const float* Qg    = g_Qh + (((size_t)b * Hh + h) * Nn + q0) * DHd;
    const float* Kb    = g_Kh + ((size_t)b * Hh + h) * Nn * DHd;
    const float* Vb    = g_Vh + ((size_t)b * Hh + h) * Nn * DHd;
    const float* biasb = bias + ((size_t)b * Nn + q0) * Nn;

    // load Q tile (natural [r][d], stride 65)
    #pragma unroll
    for (int it = 0; it < 4; it++) {
        int idx = t + it * 256;           // float4 index, 1024 total
        int r = idx >> 4, c4 = (idx & 15) * 4;
        float4 v = *(const float4*)(Qg + r * DHd + c4);
        float* p = Qs + r * LDPAD + c4;
        p[0] = v.x; p[1] = v.y; p[2] = v.z; p[3] = v.w;
    }
    if (t < 64) { mrow[t] = -INFINITY; lrow[t] = 0.0f; }

    float o[4][4] = {};
    __syncthreads();

    for (int kt = 0; kt < Nn / 64; kt++) {
        const float* Kg = Kb + (size_t)kt * 64 * DHd;
        const float* Vg = Vb + (size_t)kt * 64 * DHd;
        #pragma unroll
        for (int it = 0; it < 4; it++) {
            int idx = t + it * 256;
            int r = idx >> 4, c4 = (idx & 15) * 4;
            float4 kv = *(const float4*)(Kg + r * DHd + c4);
            float4 vv = *(const float4*)(Vg + r * DHd + c4);
            float* pk = Ks + r * LDPAD + c4;
            pk[0] = kv.x; pk[1] = kv.y; pk[2] = kv.z; pk[3] = kv.w;
            float* pv = Vs + r * LDPAD + c4;
            pv[0] = vv.x; pv[1] = vv.y; pv[2] = vv.z; pv[3] = vv.w;
        }
        __syncthreads();

        // S = Q K^T  (reduction over d; Qs broadcast loads, Ks 2-way)
        float s[4][4] = {};
        #pragma unroll 8
        for (int d = 0; d < 64; d++) {
            float rq[4], rk[4];
            #pragma unroll
            for (int i = 0; i < 4; i++) rq[i] = Qs[(ty * 4 + i) * LDPAD + d];
            #pragma unroll
            for (int j = 0; j < 4; j++) rk[j] = Ks[(tx * 4 + j) * LDPAD + d];
            #pragma unroll
            for (int i = 0; i < 4; i++)
                #pragma unroll
                for (int j = 0; j < 4; j++)
                    s[i][j] += rq[i] * rk[j];
        }

        // scale + bias, store S tile
        #pragma unroll
        for (int i = 0; i < 4; i++) {
            const float4 bv = *(const float4*)(biasb + (size_t)(ty * 4 + i) * Nn
                                               + kt * 64 + tx * 4);
            float* srow = Ss + (ty * 4 + i) * LDPAD + tx * 4;
            srow[0] = s[i][0] * 0.125f + bv.x;
            srow[1] = s[i][1] * 0.125f + bv.y;
            srow[2] = s[i][2] * 0.125f + bv.z;
            srow[3] = s[i][3] * 0.125f + bv.w;
        }
        __syncthreads();

        // --- online softmax ---
        {
            int r = t & 63, ch = t >> 6;
            const float* row = Ss + r * LDPAD + ch * 16;
            float mx = row[0];
            #pragma unroll
            for (int c = 1; c < 16; c++) mx = fmaxf(mx, row[c]);
            red[ch * 64 + r] = mx;
        }
        __syncthreads();
        if (t < 64) {
            float tm = fmaxf(fmaxf(red[t], red[64 + t]),
                             fmaxf(red[128 + t], red[192 + t]));
            float old = mrow[t];
            float nm  = fmaxf(old, tm);
            scl[t]  = __expf(old - nm);
            mrow[t] = nm;
        }
        __syncthreads();
        {
            int r = t & 63, ch = t >> 6;
            float m = mrow[r];
            float* row = Ss + r * LDPAD + ch * 16;
            float sum = 0.0f;
            #pragma unroll
            for (int c = 0; c < 16; c++) {
                float p = __expf(row[c] - m);
                row[c] = p;
                sum += p;
            }
            red[ch * 64 + r] = sum;
        }
        __syncthreads();
        if (t < 64)
            lrow[t] = lrow[t] * scl[t] + red[t] + red[64 + t] + red[128 + t] + red[192 + t];

        // --- O = O*scale + P @ V ---
        float sc[4];
        #pragma unroll
        for (int i = 0; i < 4; i++) sc[i] = scl[ty * 4 + i];
        #pragma unroll
        for (int i = 0; i < 4; i++)
            #pragma unroll
            for (int j = 0; j < 4; j++)
                o[i][j] *= sc[i];
        #pragma unroll 8
        for (int c = 0; c < 64; c++) {
            float rp[4], rv[4];
            #pragma unroll
            for (int i = 0; i < 4; i++) rp[i] = Ss[(ty * 4 + i) * LDPAD + c];
            #pragma unroll
            for (int j = 0; j < 4; j++) rv[j] = Vs[c * LDPAD + tx * 4 + j];
            #pragma unroll
            for (int i = 0; i < 4; i++)
                #pragma unroll
                for (int j = 0; j < 4; j++)
                    o[i][j] += rp[i] * rv[j];
        }
        __syncthreads();
    }

    // finalize: divide by l, write ctx (B,N,D), col = h*64 + dh
    #pragma unroll
    for (int i = 0; i < 4; i++) {
        float rl = 1.0f / lrow[ty * 4 + i];
        int n = q0 + ty * 4 + i;
        float4 v4 = make_float4(o[i][0] * rl, o[i][1] * rl,
                                o[i][2] * rl, o[i][3] * rl);
        *(float4*)(g_ctx + ((size_t)b * Nn + n) * Dd + h * DHd + tx * 4) = v4;
    }
}

// ---------------------------------------------------------------------------
// Kernel 3: output projection (d_out = ctx @ Wo^T + bo), same tiling as K1.
// ---------------------------------------------------------------------------
__global__ __launch_bounds__(256) void oproj_kernel(
    const float* __restrict__ Wo, const float* __restrict__ bo,
    float* __restrict__ out)
{
    const int t  = threadIdx.x;
    const int tx = t & 15;
    const int ty = t >> 4;
    const int bx = blockIdx.x;   // column tile, 0..7
    const int by = blockIdx.y;   // row tile, 0..127

    __shared__ float Xs[64][17];
    __shared__ float Ws[64][17];

    const int m0 = by * 64;
    const int n0 = bx * 64;

    float acc[4][4] = {};

    const int lr = t >> 2;
    const int lk = (t & 3) * 4;

    for (int k0 = 0; k0 < Dd; k0 += 16) {
        float4 xa = *(const float4*)(g_ctx + (size_t)(m0 + lr) * Dd + k0 + lk);
        float4 wa = *(const float4*)(Wo   + (size_t)(n0 + lr) * Dd + k0 + lk);
        Xs[lr][lk + 0] = xa.x; Xs[lr][lk + 1] = xa.y;
        Xs[lr][lk + 2] = xa.z; Xs[lr][lk + 3] = xa.w;
        Ws[lr][lk + 0] = wa.x; Ws[lr][lk + 1] = wa.y;
        Ws[lr][lk + 2] = wa.z; Ws[lr][lk + 3] = wa.w;
        __syncthreads();
        #pragma unroll
        for (int kk = 0; kk < 16; kk++) {
            float rx[4], rw[4];
            #pragma unroll
            for (int i = 0; i < 4; i++) rx[i] = Xs[ty * 4 + i][kk];
            #pragma unroll
            for (int j = 0; j < 4; j++) rw[j] = Ws[tx * 4 + j][kk];
            #pragma unroll
            for (int i = 0; i < 4; i++)
                #pragma unroll
                for (int j = 0; j < 4; j++)
                    acc[i][j] += rx[i] * rw[j];
        }
        __syncthreads();
    }

    #pragma unroll
    for (int i = 0; i < 4; i++) {
        int m = m0 + ty * 4 + i;
        float4 v4 = make_float4(acc[i][0] + bo[n0 + tx * 4 + 0],
                                acc[i][1] + bo[n0 + tx * 4 + 1],
                                acc[i][2] + bo[n0 + tx * 4 + 2],
                                acc[i][3] + bo[n0 + tx * 4 + 3]);
        *(float4*)(out + (size_t)m * Dd + n0 + tx * 4) = v4;
    }
}

// ---------------------------------------------------------------------------
extern "C" void kernel_launch(void* const* d_in, const int* in_sizes, int n_in,
                              void* d_out, int out_size)
{
    (void)in_sizes; (void)n_in; (void)out_size;
    const float* x    = (const float*)d_in[0];
    const float* bias = (const float*)d_in[1];
    const float* Wq   = (const float*)d_in[2];
    const float* bq   = (const float*)d_in[3];
    const float* Wk   = (const float*)d_in[4];
    const float* bk   = (const float*)d_in[5];
    const float* Wv   = (const float*)d_in[6];
    const float* bv   = (const float*)d_in[7];
    const float* Wo   = (const float*)d_in[8];
    const float* bo   = (const float*)d_in[9];
    const float* qg   = (const float*)d_in[10];
    const float* qb   = (const float*)d_in[11];
    const float* kg   = (const float*)d_in[12];
    const float* kb   = (const float*)d_in[13];
    float* out = (float*)d_out;

    cudaFuncSetAttribute(attn_kernel,
                         cudaFuncAttributeMaxDynamicSharedMemorySize, SMEM_ATTN);

    qkv_kernel<<<dim3(Dd / 64, (Bb * Nn) / 64, 3), 256>>>(
        x, Wq, bq, Wk, bk, Wv, bv, qg, qb, kg, kb);
    attn_kernel<<<dim3(Nn / 64, Bb * Hh), 256, SMEM_ATTN>>>(bias);
    oproj_kernel<<<dim3(Dd / 64, (Bb * Nn) / 64), 256>>>(Wo, bo, out);
}